// round 12
// baseline (speedup 1.0000x reference)
#include <cuda_runtime.h>
#include <cuda_bf16.h>
#include <cstdint>

#define MAX_NODES 170000
#define IN_DIM    64
#define OUT_DIM   40
#define CSR_CAP   64     // per-node bucket capacity; deg~Poisson(7), max<<64

// Scratch (device globals — no allocation allowed in kernel_launch).
// g_cnt is zero at entry of every run: zero-initialized at module load, and
// k_aggregate re-zeroes every entry at the end of each run.
__device__ float g_hp[(size_t)MAX_NODES * OUT_DIM];   // UNNORMED feats@W^T [N,40]
__device__ float g_norm[MAX_NODES];                   // rsqrt(max(deg,1))
__device__ int   g_cnt[MAX_NODES];                    // in-degree / bucket fill count
__device__ int   g_csr[(size_t)MAX_NODES * CSR_CAP];  // bucketed CSR: src ids per dst

// ---- packed f32x2 helpers (Blackwell FFMA2 via PTX) ------------------------
__device__ __forceinline__ unsigned long long pack2(float x, float y) {
    unsigned long long r;
    asm("mov.b64 %0, {%1, %2};" : "=l"(r) : "f"(x), "f"(y));
    return r;
}
__device__ __forceinline__ void unpack2(unsigned long long v, float& x, float& y) {
    asm("mov.b64 {%0, %1}, %2;" : "=f"(x), "=f"(y) : "l"(v));
}
__device__ __forceinline__ void fma2(unsigned long long& d,
                                     unsigned long long a, unsigned long long b) {
    asm("fma.rn.f32x2 %0, %1, %2, %3;" : "=l"(d) : "l"(a), "l"(b), "l"(d));
}

// Fused-grid split: every GROUP consecutive blocks = CSR_PER csr + PROJ_PER proj
#define GROUP    15
#define CSR_PER  7
#define PROJ_PER 8

// ---------------------------------------------------------------------------
// K1: FUSED CSR-build + projection (block-split, 256 threads).
// CSR blocks: 1 int4 (4 edges) per thread = 1024 edges/block.
// Projection blocks: 128 nodes, 8 warps x 5 columns, lane owns 4 nodes.
//   fs4[d][lane]: conflict-free LDS.128 per (d, warp)
//   Ws[c][d]:     float4 broadcast loads
//   10 u64 accumulators/thread (5 cols x lo/hi pair) -> low reg pressure.
// ---------------------------------------------------------------------------
__global__ __launch_bounds__(256)
void k_fused(const int4* __restrict__ src4, const int4* __restrict__ dst4,
             int E4, const float* __restrict__ feats,
             const float* __restrict__ W, int N, int projBlocks) {
    const int bid = blockIdx.x;
    const int q = bid / GROUP, r = bid % GROUP;
    const int tid = threadIdx.x;              // 0..255

    if (r < CSR_PER) {
        // ---------------- CSR part: 4 edges (1 int4) per thread ----------
        const int csr_bid = q * CSR_PER + r;
        int i = csr_bid * 256 + tid;
        if (i < E4) {
            int4 s = __ldg(&src4[i]);
            int4 d = __ldg(&dst4[i]);
            int p0 = atomicAdd(&g_cnt[d.x], 1);
            int p1 = atomicAdd(&g_cnt[d.y], 1);
            int p2 = atomicAdd(&g_cnt[d.z], 1);
            int p3 = atomicAdd(&g_cnt[d.w], 1);
            if (p0 < CSR_CAP) g_csr[(size_t)d.x * CSR_CAP + p0] = s.x;
            if (p1 < CSR_CAP) g_csr[(size_t)d.y * CSR_CAP + p1] = s.y;
            if (p2 < CSR_CAP) g_csr[(size_t)d.z * CSR_CAP + p2] = s.z;
            if (p3 < CSR_CAP) g_csr[(size_t)d.w * CSR_CAP + p3] = s.w;
        }
        return;
    }

    // ---------------- Projection part: 128 nodes per block ----------------
    const int pbid = q * PROJ_PER + (r - CSR_PER);
    if (pbid >= projBlocks) return;

    __shared__ float4 fs4[IN_DIM][33];        // [d][lane], pad to kill store conflicts
    __shared__ float  Ws[OUT_DIM * 68];       // W rows, stride 68

    const int node0 = pbid * 128;
    const int nrows = min(128, N - node0);

    // Fill W (2560 floats, 10 per thread)
    for (int i = tid; i < OUT_DIM * IN_DIM; i += 256) {
        int c = i >> 6, d = i & 63;
        Ws[c * 68 + d] = W[i];
    }
    // Fill feats transposed: coalesced float4 global reads
    {
        const float4* __restrict__ f4 = reinterpret_cast<const float4*>(feats);
        for (int i = tid; i < nrows * 16; i += 256) {
            int rr = i >> 4, qq = i & 15;
            float4 v = __ldg(&f4[(size_t)(node0 + rr) * 16 + qq]);
            int d0 = qq * 4;
            int ln = rr >> 2, comp = rr & 3;
            reinterpret_cast<float*>(&fs4[d0 + 0][ln])[comp] = v.x;
            reinterpret_cast<float*>(&fs4[d0 + 1][ln])[comp] = v.y;
            reinterpret_cast<float*>(&fs4[d0 + 2][ln])[comp] = v.z;
            reinterpret_cast<float*>(&fs4[d0 + 3][ln])[comp] = v.w;
        }
    }
    __syncthreads();

    const int lane = tid & 31, warp = tid >> 5;  // 8 warps
    const int c0 = warp * 5;                     // 5 columns per warp

    unsigned long long acc_lo[5], acc_hi[5];
#pragma unroll
    for (int j = 0; j < 5; j++) { acc_lo[j] = pack2(0.f, 0.f); acc_hi[j] = pack2(0.f, 0.f); }

#pragma unroll
    for (int dq = 0; dq < 16; dq++) {
        const int d = dq * 4;
        float4 f0 = fs4[d + 0][lane];
        float4 f1 = fs4[d + 1][lane];
        float4 f2 = fs4[d + 2][lane];
        float4 f3 = fs4[d + 3][lane];
        unsigned long long f0l = pack2(f0.x, f0.y), f0h = pack2(f0.z, f0.w);
        unsigned long long f1l = pack2(f1.x, f1.y), f1h = pack2(f1.z, f1.w);
        unsigned long long f2l = pack2(f2.x, f2.y), f2h = pack2(f2.z, f2.w);
        unsigned long long f3l = pack2(f3.x, f3.y), f3h = pack2(f3.z, f3.w);
#pragma unroll
        for (int j = 0; j < 5; j++) {
            float4 w = *reinterpret_cast<const float4*>(&Ws[(c0 + j) * 68 + d]);
            unsigned long long w0 = pack2(w.x, w.x);
            unsigned long long w1 = pack2(w.y, w.y);
            unsigned long long w2 = pack2(w.z, w.z);
            unsigned long long w3 = pack2(w.w, w.w);
            fma2(acc_lo[j], f0l, w0); fma2(acc_hi[j], f0h, w0);
            fma2(acc_lo[j], f1l, w1); fma2(acc_hi[j], f1h, w1);
            fma2(acc_lo[j], f2l, w2); fma2(acc_hi[j], f2h, w2);
            fma2(acc_lo[j], f3l, w3); fma2(acc_hi[j], f3h, w3);
        }
    }

    // Unpack: v[t][j] = output for node (4*lane+t), col (c0+j)
    float v[4][5];
#pragma unroll
    for (int j = 0; j < 5; j++) {
        unpack2(acc_lo[j], v[0][j], v[1][j]);
        unpack2(acc_hi[j], v[2][j], v[3][j]);
    }
#pragma unroll
    for (int t = 0; t < 4; t++) {
        int nl = 4 * lane + t;
        if (nl < nrows) {
            float* dst = &g_hp[(size_t)(node0 + nl) * OUT_DIM + c0];
#pragma unroll
            for (int j = 0; j < 5; j++) dst[j] = v[t][j];
        }
    }
}

// ---------------------------------------------------------------------------
// K2: norm table from counts (tiny, ~2us)
// ---------------------------------------------------------------------------
__global__ void k_norm(int N) {
    int i = blockIdx.x * blockDim.x + threadIdx.x;
    if (i < N) g_norm[i] = rsqrtf(fmaxf((float)g_cnt[i], 1.0f));
}

// ---------------------------------------------------------------------------
// K3: gather-aggregate, 10 lanes per dst row (one float4 chunk per lane).
//   out[d,:] = norm[d] * sum_i norm[s_i] * hp_un[s_i,:] + b
// Lane 0 re-zeroes cnt[d] for the next graph replay.
// ---------------------------------------------------------------------------
__global__ __launch_bounds__(640, 3)
void k_aggregate(float* __restrict__ out, const float4* __restrict__ b4, int N) {
    const int gt = blockIdx.x * 640 + threadIdx.x;
    const int d  = gt / 10;
    const int k  = gt - d * 10;          // 0..9
    if (d >= N) return;

    int cnt = g_cnt[d];
    const float nm = __ldg(&g_norm[d]);
    int m = cnt < CSR_CAP ? cnt : CSR_CAP;
    const int4* __restrict__ row4 =
        reinterpret_cast<const int4*>(g_csr + (size_t)d * CSR_CAP);
    const float4* __restrict__ hp4 = reinterpret_cast<const float4*>(g_hp);

    float4 a = make_float4(0.f, 0.f, 0.f, 0.f);

    int i = 0;
    for (; i + 4 <= m; i += 4) {
        int4 s = __ldg(&row4[i >> 2]);
        float n0 = __ldg(&g_norm[s.x]);
        float n1 = __ldg(&g_norm[s.y]);
        float n2 = __ldg(&g_norm[s.z]);
        float n3 = __ldg(&g_norm[s.w]);
        float4 u = hp4[(size_t)s.x * 10 + k];
        float4 v = hp4[(size_t)s.y * 10 + k];
        float4 w = hp4[(size_t)s.z * 10 + k];
        float4 x = hp4[(size_t)s.w * 10 + k];
        a.x += u.x * n0 + v.x * n1 + w.x * n2 + x.x * n3;
        a.y += u.y * n0 + v.y * n1 + w.y * n2 + x.y * n3;
        a.z += u.z * n0 + v.z * n1 + w.z * n2 + x.z * n3;
        a.w += u.w * n0 + v.w * n1 + w.w * n2 + x.w * n3;
    }
    const int* __restrict__ row = reinterpret_cast<const int*>(row4);
    for (; i < m; i++) {
        int s0 = __ldg(&row[i]);
        float n0 = __ldg(&g_norm[s0]);
        float4 u = hp4[(size_t)s0 * 10 + k];
        a.x += u.x * n0; a.y += u.y * n0; a.z += u.z * n0; a.w += u.w * n0;
    }

    float4 bb = __ldg(&b4[k]);
    float4 o;
    o.x = a.x * nm + bb.x; o.y = a.y * nm + bb.y;
    o.z = a.z * nm + bb.z; o.w = a.w * nm + bb.w;

    reinterpret_cast<float4*>(out + (size_t)d * OUT_DIM)[k] = o;

    if (k == 0) g_cnt[d] = 0;            // reset for next replay
}

// ---------------------------------------------------------------------------
extern "C" void kernel_launch(void* const* d_in, const int* in_sizes, int n_in,
                              void* d_out, int out_size) {
    const float* feats = (const float*)d_in[0];
    const float* W     = (const float*)d_in[1];
    const float* b     = (const float*)d_in[2];
    const int*   src   = (const int*)d_in[3];   // JAX x64 disabled -> int32
    const int*   dst   = (const int*)d_in[4];
    float* out = (float*)d_out;

    const int OUT = in_sizes[2];            // 40
    const int IN  = in_sizes[1] / OUT;      // 64
    const int N   = in_sizes[0] / IN;       // 170000
    const int E   = in_sizes[3];            // 1200000 (multiple of 4)
    (void)n_in; (void)OUT; (void)out_size;

    // K1: fused CSR + projection
    {
        int E4 = E / 4;                               // 300000
        int csrBlocks  = (E4 + 255) / 256;            // 1172
        int projBlocks = (N + 127) / 128;             // 1329
        int groups_c = (csrBlocks + CSR_PER - 1) / CSR_PER;
        int groups_p = (projBlocks + PROJ_PER - 1) / PROJ_PER;
        int groups = groups_c > groups_p ? groups_c : groups_p;
        int grid = groups * GROUP;
        k_fused<<<grid, 256>>>((const int4*)src, (const int4*)dst, E4,
                               feats, W, N, projBlocks);
    }

    // K2: norm table
    k_norm<<<(N + 511) / 512, 512>>>(N);

    // K3: gather-aggregate (10 lanes/row)
    {
        long long total = (long long)N * 10;
        int blocks = (int)((total + 639) / 640);
        k_aggregate<<<blocks, 640>>>(out, (const float4*)b, N);
    }
}

// round 13
// speedup vs baseline: 1.2565x; 1.2565x over previous
#include <cuda_runtime.h>
#include <cuda_bf16.h>
#include <cstdint>

#define MAX_NODES 170000
#define IN_DIM    64
#define OUT_DIM   40
#define CSR_CAP   64     // per-node bucket capacity; deg~Poisson(7), max<<64

// Scratch (device globals — no allocation allowed in kernel_launch).
// g_cnt is zero at entry of every run: zero-initialized at module load, and
// k_aggregate re-zeroes every entry at the end of each run.
__device__ float g_hp[(size_t)MAX_NODES * OUT_DIM];   // UNNORMED feats@W^T [N,40]
__device__ float g_norm[MAX_NODES];                   // rsqrt(max(deg,1))
__device__ int   g_cnt[MAX_NODES];                    // in-degree / bucket fill count
__device__ int   g_csr[(size_t)MAX_NODES * CSR_CAP];  // bucketed CSR: src ids per dst

#define CSR_BLOCKS 148   // one persistent CSR block per SM

// ---------------------------------------------------------------------------
// K1: FUSED kernel.
//   bid < CSR_BLOCKS : persistent CSR build — grid-stride int4 loop over
//     edges; latency-bound on ATOMG but saturates the LTS atomic ALUs from a
//     single block-slot per SM while the remaining slots run the projection.
//   bid >= CSR_BLOCKS : register-tiled projection, 128 nodes x 40 cols/block.
//     warp = 8-column group, lane = 4-node group; per depth d:
//       1 conflict-free LDS.128 (fs4[d][lane]) + 2 broadcast LDS.128 (Wt)
//       + 32 FFMA into a 4x8 register tile  -> FMA-throughput bound.
// ---------------------------------------------------------------------------
__global__ __launch_bounds__(160)
void k_fused(const int4* __restrict__ src4, const int4* __restrict__ dst4,
             int E4, const int* __restrict__ src, const int* __restrict__ dst,
             int E, const float* __restrict__ feats,
             const float* __restrict__ W, int N) {
    const int bid = blockIdx.x;
    const int tid = threadIdx.x;              // 0..159

    if (bid < CSR_BLOCKS) {
        // -------------------- CSR sidecar --------------------
        const int stride = CSR_BLOCKS * 160;
        for (int i = bid * 160 + tid; i < E4; i += stride) {
            int4 s = __ldg(&src4[i]);
            int4 d = __ldg(&dst4[i]);
            int p0 = atomicAdd(&g_cnt[d.x], 1);
            int p1 = atomicAdd(&g_cnt[d.y], 1);
            int p2 = atomicAdd(&g_cnt[d.z], 1);
            int p3 = atomicAdd(&g_cnt[d.w], 1);
            if (p0 < CSR_CAP) g_csr[(size_t)d.x * CSR_CAP + p0] = s.x;
            if (p1 < CSR_CAP) g_csr[(size_t)d.y * CSR_CAP + p1] = s.y;
            if (p2 < CSR_CAP) g_csr[(size_t)d.z * CSR_CAP + p2] = s.z;
            if (p3 < CSR_CAP) g_csr[(size_t)d.w * CSR_CAP + p3] = s.w;
        }
        // tail edges (E not multiple of 4)
        if (bid == 0 && tid < 4) {
            int t = E4 * 4 + tid;
            if (t < E) {
                int s = src[t], d = dst[t];
                int pos = atomicAdd(&g_cnt[d], 1);
                if (pos < CSR_CAP) g_csr[(size_t)d * CSR_CAP + pos] = s;
            }
        }
        return;
    }

    // -------------------- Projection: 128 nodes per block --------------------
    const int pbid = bid - CSR_BLOCKS;

    __shared__ float4 fs4[IN_DIM][33];        // fs4[d][lane]: 4 nodes' feats at depth d
    __shared__ float  Wt[IN_DIM][44];         // Wt[d][c] = W[c][d]; stride 44 (16B-aligned)

    const int node0 = pbid * 128;
    const int nrows = min(128, N - node0);

    // Fill Wt transposed (2560 floats, 16/thread)
    for (int i = tid; i < OUT_DIM * IN_DIM; i += 160) {
        int c = i >> 6, d = i & 63;
        Wt[d][c] = W[i];
    }
    // Fill feats transposed: coalesced float4 global reads
    {
        const float4* __restrict__ f4 = reinterpret_cast<const float4*>(feats);
        for (int i = tid; i < nrows * 16; i += 160) {
            int rr = i >> 4, qq = i & 15;
            float4 v = __ldg(&f4[(size_t)(node0 + rr) * 16 + qq]);
            int d0 = qq * 4, ln = rr >> 2, comp = rr & 3;
            reinterpret_cast<float*>(&fs4[d0 + 0][ln])[comp] = v.x;
            reinterpret_cast<float*>(&fs4[d0 + 1][ln])[comp] = v.y;
            reinterpret_cast<float*>(&fs4[d0 + 2][ln])[comp] = v.z;
            reinterpret_cast<float*>(&fs4[d0 + 3][ln])[comp] = v.w;
        }
    }
    __syncthreads();

    const int lane = tid & 31, warp = tid >> 5;   // 5 warps
    const int c0 = warp * 8;                      // 8 columns per warp

    float acc[4][8];
#pragma unroll
    for (int t = 0; t < 4; t++)
#pragma unroll
        for (int j = 0; j < 8; j++) acc[t][j] = 0.f;

#pragma unroll 8
    for (int d = 0; d < IN_DIM; d++) {
        float4 f  = fs4[d][lane];
        float4 wA = *reinterpret_cast<const float4*>(&Wt[d][c0]);
        float4 wB = *reinterpret_cast<const float4*>(&Wt[d][c0 + 4]);
        float fv[4] = {f.x, f.y, f.z, f.w};
        float wv[8] = {wA.x, wA.y, wA.z, wA.w, wB.x, wB.y, wB.z, wB.w};
#pragma unroll
        for (int t = 0; t < 4; t++)
#pragma unroll
            for (int j = 0; j < 8; j++)
                acc[t][j] += fv[t] * wv[j];
    }

    // Store: node (node0 + 4*lane + t), cols [c0, c0+8). 32B-aligned -> 2x STG.128
#pragma unroll
    for (int t = 0; t < 4; t++) {
        int nl = 4 * lane + t;
        if (nl < nrows) {
            float4* dst = reinterpret_cast<float4*>(
                &g_hp[(size_t)(node0 + nl) * OUT_DIM + c0]);
            dst[0] = make_float4(acc[t][0], acc[t][1], acc[t][2], acc[t][3]);
            dst[1] = make_float4(acc[t][4], acc[t][5], acc[t][6], acc[t][7]);
        }
    }
}

// ---------------------------------------------------------------------------
// K2: norm table from counts (tiny, ~2us)
// ---------------------------------------------------------------------------
__global__ void k_norm(int N) {
    int i = blockIdx.x * blockDim.x + threadIdx.x;
    if (i < N) g_norm[i] = rsqrtf(fmaxf((float)g_cnt[i], 1.0f));
}

// ---------------------------------------------------------------------------
// K3: gather-aggregate, 10 lanes per dst row (one float4 chunk per lane).
//   out[d,:] = norm[d] * sum_i norm[s_i] * hp_un[s_i,:] + b
// Lane 0 re-zeroes cnt[d] for the next graph replay.
// ---------------------------------------------------------------------------
__global__ __launch_bounds__(640, 3)
void k_aggregate(float* __restrict__ out, const float4* __restrict__ b4, int N) {
    const int gt = blockIdx.x * 640 + threadIdx.x;
    const int d  = gt / 10;
    const int k  = gt - d * 10;          // 0..9
    if (d >= N) return;

    int cnt = g_cnt[d];
    const float nm = __ldg(&g_norm[d]);
    int m = cnt < CSR_CAP ? cnt : CSR_CAP;
    const int4* __restrict__ row4 =
        reinterpret_cast<const int4*>(g_csr + (size_t)d * CSR_CAP);
    const float4* __restrict__ hp4 = reinterpret_cast<const float4*>(g_hp);

    float4 a = make_float4(0.f, 0.f, 0.f, 0.f);

    int i = 0;
    for (; i + 4 <= m; i += 4) {
        int4 s = __ldg(&row4[i >> 2]);
        float n0 = __ldg(&g_norm[s.x]);
        float n1 = __ldg(&g_norm[s.y]);
        float n2 = __ldg(&g_norm[s.z]);
        float n3 = __ldg(&g_norm[s.w]);
        float4 u = hp4[(size_t)s.x * 10 + k];
        float4 v = hp4[(size_t)s.y * 10 + k];
        float4 w = hp4[(size_t)s.z * 10 + k];
        float4 x = hp4[(size_t)s.w * 10 + k];
        a.x += u.x * n0 + v.x * n1 + w.x * n2 + x.x * n3;
        a.y += u.y * n0 + v.y * n1 + w.y * n2 + x.y * n3;
        a.z += u.z * n0 + v.z * n1 + w.z * n2 + x.z * n3;
        a.w += u.w * n0 + v.w * n1 + w.w * n2 + x.w * n3;
    }
    const int* __restrict__ row = reinterpret_cast<const int*>(row4);
    for (; i < m; i++) {
        int s0 = __ldg(&row[i]);
        float n0 = __ldg(&g_norm[s0]);
        float4 u = hp4[(size_t)s0 * 10 + k];
        a.x += u.x * n0; a.y += u.y * n0; a.z += u.z * n0; a.w += u.w * n0;
    }

    float4 bb = __ldg(&b4[k]);
    float4 o;
    o.x = a.x * nm + bb.x; o.y = a.y * nm + bb.y;
    o.z = a.z * nm + bb.z; o.w = a.w * nm + bb.w;

    reinterpret_cast<float4*>(out + (size_t)d * OUT_DIM)[k] = o;

    if (k == 0) g_cnt[d] = 0;            // reset for next replay
}

// ---------------------------------------------------------------------------
extern "C" void kernel_launch(void* const* d_in, const int* in_sizes, int n_in,
                              void* d_out, int out_size) {
    const float* feats = (const float*)d_in[0];
    const float* W     = (const float*)d_in[1];
    const float* b     = (const float*)d_in[2];
    const int*   src   = (const int*)d_in[3];   // JAX x64 disabled -> int32
    const int*   dst   = (const int*)d_in[4];
    float* out = (float*)d_out;

    const int OUT = in_sizes[2];            // 40
    const int IN  = in_sizes[1] / OUT;      // 64
    const int N   = in_sizes[0] / IN;       // 170000
    const int E   = in_sizes[3];            // 1200000
    (void)n_in; (void)OUT; (void)out_size;

    // K1: fused CSR sidecar + register-tiled projection
    {
        int E4 = E / 4;
        int projBlocks = (N + 127) / 128;   // 1329
        k_fused<<<CSR_BLOCKS + projBlocks, 160>>>(
            (const int4*)src, (const int4*)dst, E4, src, dst, E, feats, W, N);
    }

    // K2: norm table
    k_norm<<<(N + 511) / 512, 512>>>(N);

    // K3: gather-aggregate (10 lanes/row)
    {
        long long total = (long long)N * 10;
        int blocks = (int)((total + 639) / 640);
        k_aggregate<<<blocks, 640>>>(out, (const float4*)b, N);
    }
}